// round 15
// baseline (speedup 1.0000x reference)
#include <cuda_runtime.h>
#include <cuda_bf16.h>
#include <cstdint>

#define N_ROWS 16384
#define M_COLS 2048
#define D_DIM  128
#define K_CONST 0.1f
#define GAMMA_CONST 1.0f

// ======================= PTX helpers ========================================
__device__ __forceinline__ uint32_t smem_u32(const void* p) {
    uint32_t a;
    asm("{ .reg .u64 t; cvta.to.shared.u64 t, %1; cvt.u32.u64 %0, t; }" : "=r"(a) : "l"(p));
    return a;
}
#define CPA16(dst, src) \
    asm volatile("cp.async.cg.shared.global [%0], [%1], 16;" :: "r"(dst), "l"(src))
#define CPA_COMMIT() asm volatile("cp.async.commit_group;" ::: "memory")
#define CPA_WAIT1()  asm volatile("cp.async.wait_group 1;" ::: "memory")

__device__ __forceinline__ void ldsm4(uint32_t* r, uint32_t addr) {
    asm volatile("ldmatrix.sync.aligned.m8n8.x4.shared.b16 {%0,%1,%2,%3}, [%4];"
        : "=r"(r[0]), "=r"(r[1]), "=r"(r[2]), "=r"(r[3]) : "r"(addr));
}
__device__ __forceinline__ void mma16816(float* c, const uint32_t* a, uint32_t b0, uint32_t b1) {
    asm volatile("mma.sync.aligned.m16n8k16.row.col.f32.bf16.bf16.f32 "
        "{%0,%1,%2,%3}, {%4,%5,%6,%7}, {%8,%9}, {%0,%1,%2,%3};"
        : "+f"(c[0]), "+f"(c[1]), "+f"(c[2]), "+f"(c[3])
        : "r"(a[0]), "r"(a[1]), "r"(a[2]), "r"(a[3]), "r"(b0), "r"(b1));
}

// ======================= scratch device globals ==============================
__device__ __align__(16) __nv_bfloat16 g_pbf[M_COLS * D_DIM];
__device__ float  g_sum_x[D_DIM];
__device__ float  g_sum_nx2;
__device__ int    g_nx2min_bits;
__device__ float  g_nx2[N_ROWS];
__device__ float4 g_pstat[M_COLS];   // {np2, invc, psi, 0}
__device__ float  g_ustar[M_COLS];   // per-column dot gate
__device__ double g_acc;

// ======================= prep kernels ========================================
__global__ void init_kernel() {
    int t = threadIdx.x;
    if (t < D_DIM) g_sum_x[t] = 0.f;
    if (t == 0) { g_sum_nx2 = 0.f; g_acc = 0.0; g_nx2min_bits = 0x7f7fffff; }
}

// per-row ||x||^2, column sums, global min ||x||^2
__global__ void xstats_kernel(const float* __restrict__ x) {
    __shared__ float ssx[8][128];
    __shared__ float ssn[8];
    __shared__ float ssm[8];
    int lane = threadIdx.x & 31;
    int wid  = threadIdx.x >> 5;
    int base = (blockIdx.x * 8 + wid) * 8;

    float sx0 = 0.f, sx1 = 0.f, sx2 = 0.f, sx3 = 0.f;
    float snx2 = 0.f, rmin = 3.4e38f;
    #pragma unroll
    for (int rr = 0; rr < 8; ++rr) {
        int row = base + rr;
        float4 v = ((const float4*)(x + (size_t)row * D_DIM))[lane];
        float d = v.x*v.x + v.y*v.y + v.z*v.z + v.w*v.w;
        snx2 += d;
        float dr = d;
        #pragma unroll
        for (int o = 16; o; o >>= 1) dr += __shfl_xor_sync(0xffffffffu, dr, o);
        if (lane == 0) { g_nx2[row] = dr; rmin = fminf(rmin, dr); }
        sx0 += v.x; sx1 += v.y; sx2 += v.z; sx3 += v.w;
    }
    ssx[wid][lane*4+0] = sx0; ssx[wid][lane*4+1] = sx1;
    ssx[wid][lane*4+2] = sx2; ssx[wid][lane*4+3] = sx3;
    #pragma unroll
    for (int o = 16; o; o >>= 1) snx2 += __shfl_xor_sync(0xffffffffu, snx2, o);
    if (lane == 0) { ssn[wid] = snx2; ssm[wid] = rmin; }
    __syncthreads();
    if (threadIdx.x < 128) {
        float s = 0.f;
        #pragma unroll
        for (int w = 0; w < 8; ++w) s += ssx[w][threadIdx.x];
        atomicAdd(&g_sum_x[threadIdx.x], s);
    }
    if (threadIdx.x == 0) {
        float s = 0.f, m = 3.4e38f;
        #pragma unroll
        for (int w = 0; w < 8; ++w) { s += ssn[w]; m = fminf(m, ssm[w]); }
        atomicAdd(&g_sum_nx2, s);
        atomicMin(&g_nx2min_bits, __float_as_int(m));   // all positive: int-order OK
    }
}

// warp-per-column: constants + conservative dot gate u*
__global__ void pstats_kernel(const float* __restrict__ p) {
    int j    = blockIdx.x * 8 + (threadIdx.x >> 5);
    int lane = threadIdx.x & 31;
    if (j >= M_COLS) return;
    float4 v = ((const float4*)(p + (size_t)j * D_DIM))[lane];
    float4 s = ((const float4*)g_sum_x)[lane];
    float np2   = v.x*v.x + v.y*v.y + v.z*v.z + v.w*v.w;
    float sxdot = v.x*s.x + v.y*s.y + v.z*s.z + v.w*s.w;
    __nv_bfloat162 h0 = __floats2bfloat162_rn(v.x, v.y);
    __nv_bfloat162 h1 = __floats2bfloat162_rn(v.z, v.w);
    uint2 hi = make_uint2(*(uint32_t*)&h0, *(uint32_t*)&h1);
    *(uint2*)(g_pbf + (size_t)j * D_DIM + lane * 4) = hi;
    #pragma unroll
    for (int o = 16; o; o >>= 1) {
        np2   += __shfl_xor_sync(0xffffffffu, np2, o);
        sxdot += __shfl_xor_sync(0xffffffffu, sxdot, o);
    }
    if (lane == 0) {
        float m      = __int_as_float(g_nx2min_bits);       // global min ||x||^2
        float ssd    = g_sum_nx2 + (float)N_ROWS * np2 - 2.f * sxdot;
        float invc   = rsqrtf(np2 * ssd);
        float inv_np = rsqrtf(np2);
        float psi    = asinf(K_CONST * (1.f - np2) * inv_np);
        float c1     = cosf(GAMMA_CONST + psi);             // > 0
        // hinge!=0 requires ratio>c1; conservative over rows (nx2>=m):
        //   stable root: s = q/(A*(sqrt(cC^2+q)+cC)), q = A(1-np2)(1-np2*m), u* = (E-s^2)/2
        float cC = c1 * sqrtf(np2 * ssd);
        float A  = 1.f + np2;
        float E  = fmaf(np2, m, 1.f);
        float q  = A * (1.f - np2) * (1.f - np2 * m);
        float sr = q / (A * (sqrtf(fmaf(cC, cC, q)) + cC));
        float us = 0.5f * (E - sr * sr) - 1e-4f;            // safety margin
        g_pstat[j] = make_float4(np2, invc, psi, 0.f);
        g_ustar[j] = us;
    }
}

// ======================= main fused kernel ===================================
// 256 CTAs x 64-row tiles, 512 threads (16 warps: 4 row x 4 col of 16x32),
// <=64 regs/thread so 2 CTAs/SM = 32 warps/SM (RF-exact).
// SMEM map (bytes):
#define SM_RED 0                       // 16 floats + pad
#define SM_US  128                     // ustar: 2048 * 4 = 8192
#define SM_A   (SM_US + 8192)          // 64x128 bf16 = 16384
#define SM_B   (SM_A + 16384)          // 2 x 32768
#define SMEM_TOTAL (SM_B + 2 * 32768)  // 90240  (x2 CTAs = 180KB, fits)
#define NTHREADS 512

// Tile stored as [rows][16 chunks of 16B]; phys chunk = c ^ (row & 7).
__device__ __forceinline__ uint32_t sw_off(int row, int c) {
    return (uint32_t)(row * 256 + ((c ^ (row & 7)) << 4));
}

__device__ __forceinline__ void load_b_tile(uint32_t sb, int buf, int t) {
    const int tid = threadIdx.x;
    const uint32_t bh = sb + SM_B + buf * 32768u;
    const size_t rbase = (size_t)t * 128 * D_DIM;
    #pragma unroll
    for (int i = 0; i < 4; ++i) {
        int idx = tid + i * NTHREADS;
        int row = idx >> 4, c = idx & 15;
        uint32_t off = sw_off(row, c);
        size_t src = rbase + (size_t)row * D_DIM + c * 8;
        CPA16(bh + off, (const void*)(g_pbf + src));
    }
}

// fast acos via A&S 4.4.45 (|err| <= 2e-8), sqrt.approx
__device__ __forceinline__ float acos_fast(float x) {
    float ax = fabsf(x);
    float s;
    asm("sqrt.approx.f32 %0, %1;" : "=f"(s) : "f"(1.0f - ax));
    float p = -0.0012624911f;
    p = fmaf(p, ax,  0.0066700901f);
    p = fmaf(p, ax, -0.0170881256f);
    p = fmaf(p, ax,  0.0308918810f);
    p = fmaf(p, ax, -0.0501743046f);
    p = fmaf(p, ax,  0.0889789874f);
    p = fmaf(p, ax, -0.2145988016f);
    p = fmaf(p, ax,  1.5707963050f);
    float r = s * p;
    return (x < 0.f) ? (3.14159265358979f - r) : r;
}

__global__ void __launch_bounds__(NTHREADS, 2)
main_kernel(const float* __restrict__ x, const int* __restrict__ labels) {
    extern __shared__ char smem[];
    const uint32_t sb = smem_u32(smem);
    const int tid = threadIdx.x;
    const int wid = tid >> 5, lane = tid & 31;
    const int rowBase = blockIdx.x * 64;
    const int warpRow = (wid & 3) * 16;      // 4 row-groups of 16
    const int warpCol = (wid >> 2) * 32;     // 4 col-groups of 32
    const int gid = lane >> 2, tig = lane & 3;
    const int lrow = lane & 15, side = lane >> 4, l7 = lane & 7;

    // ---- async group 0: ustar + B tile 0; group 1: B tile 1 ----
    if (tid < 512) CPA16(sb + SM_US + tid * 16, (const void*)(g_ustar + tid * 4));
    load_b_tile(sb, 0, 0);
    CPA_COMMIT();                 // group: tile 0 (+ustar)
    load_b_tile(sb, 1, 1);
    CPA_COMMIT();                 // group: tile 1

    // ---- A: load fp32 x tile (64 rows), round to bf16 in smem ----
    #pragma unroll
    for (int i = 0; i < 2; ++i) {
        int idx = tid + i * NTHREADS;          // 1024 16B-chunks
        int row = idx >> 4, c = idx & 15;
        const float4* src = (const float4*)(x + (size_t)(rowBase + row) * D_DIM + c * 8);
        float4 a = src[0], b = src[1];
        __nv_bfloat162 h0 = __floats2bfloat162_rn(a.x, a.y);
        __nv_bfloat162 h1 = __floats2bfloat162_rn(a.z, a.w);
        __nv_bfloat162 h2 = __floats2bfloat162_rn(b.x, b.y);
        __nv_bfloat162 h3 = __floats2bfloat162_rn(b.z, b.w);
        uint4 h = make_uint4(*(uint32_t*)&h0, *(uint32_t*)&h1,
                             *(uint32_t*)&h2, *(uint32_t*)&h3);
        *(uint4*)(smem + SM_A + sw_off(row, c)) = h;
    }

    // ---- per-thread row constants: rows warpRow+gid, warpRow+gid+8 ----
    float bx2[2]; int lab2[2];
    #pragma unroll
    for (int h = 0; h < 2; ++h) {
        int r = rowBase + warpRow + gid + h * 8;
        bx2[h]  = g_nx2[r];
        lab2[h] = labels[r];
    }

    __syncthreads();   // A smem visible to all warps

    const uint32_t AH = sb + SM_A;
    const float* usp = (const float*)(smem + SM_US);
    float acc[4][4];   // [nt][q], q = h*2 + e
    float local = 0.f;

    for (int t = 0; t < 16; ++t) {
        CPA_WAIT1();          // oldest pending group (tile t) complete
        __syncthreads();

        // ---- MMA: 16x32 warp tile, B from buf t&1 ----
        {
            const uint32_t BH = sb + SM_B + (t & 1) * 32768u;
            #pragma unroll
            for (int nt = 0; nt < 4; ++nt)
                #pragma unroll
                for (int q = 0; q < 4; ++q) acc[nt][q] = 0.f;
            #pragma unroll
            for (int ks = 0; ks < 8; ++ks) {
                const uint32_t kc = (uint32_t)(((ks * 2 + side) ^ l7) << 4);
                uint32_t a0[4];
                ldsm4(a0, AH + (uint32_t)(warpRow + lrow) * 256 + kc);
                #pragma unroll
                for (int tp = 0; tp < 2; ++tp) {
                    uint32_t b[4];
                    ldsm4(b, BH + (uint32_t)(warpCol + tp * 16 + lrow) * 256 + kc);
                    mma16816(acc[tp*2],   a0, b[0], b[2]);
                    mma16816(acc[tp*2+1], a0, b[1], b[3]);
                }
            }
        }

        // ---- epilogue: per-column dot gate; cold path rare ----
        {
            const int colBase = t * 128 + warpCol;
            #pragma unroll
            for (int nt = 0; nt < 4; ++nt) {
                const int ci = colBase + nt * 8 + tig * 2;
                float2 us = *(const float2*)(usp + ci);
                float usmin = fminf(us.x, us.y);
                float d00 = acc[nt][0], d01 = acc[nt][1];
                float d10 = acc[nt][2], d11 = acc[nt][3];
                float dmax = fmaxf(fmaxf(d00, d01), fmaxf(d10, d11));
                if (dmax > usmin) {                                // cold, ~never
                    #pragma unroll
                    for (int e = 0; e < 2; ++e) {
                        float usv = e ? us.y : us.x;
                        float dv[2] = { e ? d01 : d00, e ? d11 : d10 };
                        const int c = ci + e;
                        #pragma unroll
                        for (int h = 0; h < 2; ++h) {
                            float dot = dv[h];
                            if (dot > usv && c != lab2[h]) {
                                float4 ps  = g_pstat[c];
                                float bxv  = bx2[h];
                                float num  = fmaf(ps.x, dot - (1.f + bxv), dot);
                                float tt   = fmaf(-2.f, dot, fmaf(ps.x, bxv, 1.f));
                                float ratio= num * ps.y * rsqrtf(tt);
                                float rc   = fminf(1.f, fmaxf(-1.f, ratio));
                                float ang  = fmaxf(0.f, acos_fast(rc) - ps.z);
                                local += fmaxf(0.f, GAMMA_CONST - ang);
                            }
                        }
                    }
                }
            }
            // ---- label elements (positive term), rare ownership check ----
            #pragma unroll
            for (int h = 0; h < 2; ++h) {
                unsigned d = (unsigned)(lab2[h] - colBase);
                if (d < 32u && (d & 6u) == 2u * (unsigned)tig) {
                    #pragma unroll
                    for (int nt = 0; nt < 4; ++nt)
                        if ((d >> 3) == (unsigned)nt) {
                            float dot = acc[nt][h * 2 + (d & 1u)];
                            float4 ps  = g_pstat[lab2[h]];
                            float bxv  = bx2[h];
                            float num  = fmaf(ps.x, dot - (1.f + bxv), dot);
                            float tt   = fmaf(-2.f, dot, fmaf(ps.x, bxv, 1.f));
                            float ratio= num * ps.y * rsqrtf(tt);
                            float rc   = fminf(1.f, fmaxf(-1.f, ratio));
                            local += fmaxf(0.f, acos_fast(rc) - ps.z);
                        }
                }
            }
        }

        __syncthreads();      // all warps done reading buf t&1
        if (t < 14) load_b_tile(sb, t & 1, t + 2);
        CPA_COMMIT();         // uniform group count
    }

    // ---- block reduction -> one double atomic per CTA ----
    #pragma unroll
    for (int o = 16; o; o >>= 1) local += __shfl_xor_sync(0xffffffffu, local, o);
    float* red = (float*)(smem + SM_RED);
    if (lane == 0) red[wid] = local;
    __syncthreads();
    if (tid == 0) {
        float s = 0.f;
        #pragma unroll
        for (int w = 0; w < 16; ++w) s += red[w];
        atomicAdd(&g_acc, (double)s);
    }
}

__global__ void finish_kernel(float* __restrict__ out) {
    out[0] = (float)(g_acc / (double)N_ROWS);
}

// ======================= launch ==============================================
extern "C" void kernel_launch(void* const* d_in, const int* in_sizes, int n_in,
                              void* d_out, int out_size) {
    const float* x      = (const float*)d_in[0];
    const float* p      = (const float*)d_in[1];
    const int*   labels = (const int*)d_in[2];
    float* out = (float*)d_out;

    cudaFuncSetAttribute(main_kernel, cudaFuncAttributeMaxDynamicSharedMemorySize, SMEM_TOTAL);

    init_kernel<<<1, 128>>>();
    xstats_kernel<<<256, 256>>>(x);
    pstats_kernel<<<256, 256>>>(p);
    main_kernel<<<256, NTHREADS, SMEM_TOTAL>>>(x, labels);
    finish_kernel<<<1, 1>>>(out);
}

// round 16
// speedup vs baseline: 1.0661x; 1.0661x over previous
#include <cuda_runtime.h>
#include <cuda_bf16.h>
#include <cstdint>

#define N_ROWS 16384
#define M_COLS 2048
#define D_DIM  128
#define K_CONST 0.1f
#define GAMMA_CONST 1.0f

// ======================= PTX helpers ========================================
__device__ __forceinline__ uint32_t smem_u32(const void* p) {
    uint32_t a;
    asm("{ .reg .u64 t; cvta.to.shared.u64 t, %1; cvt.u32.u64 %0, t; }" : "=r"(a) : "l"(p));
    return a;
}
#define CPA16(dst, src) \
    asm volatile("cp.async.cg.shared.global [%0], [%1], 16;" :: "r"(dst), "l"(src))
#define CPA_COMMIT() asm volatile("cp.async.commit_group;" ::: "memory")
#define CPA_WAIT1()  asm volatile("cp.async.wait_group 1;" ::: "memory")

__device__ __forceinline__ void ldsm4(uint32_t* r, uint32_t addr) {
    asm volatile("ldmatrix.sync.aligned.m8n8.x4.shared.b16 {%0,%1,%2,%3}, [%4];"
        : "=r"(r[0]), "=r"(r[1]), "=r"(r[2]), "=r"(r[3]) : "r"(addr));
}
__device__ __forceinline__ void mma16816(float* c, const uint32_t* a, uint32_t b0, uint32_t b1) {
    asm volatile("mma.sync.aligned.m16n8k16.row.col.f32.bf16.bf16.f32 "
        "{%0,%1,%2,%3}, {%4,%5,%6,%7}, {%8,%9}, {%0,%1,%2,%3};"
        : "+f"(c[0]), "+f"(c[1]), "+f"(c[2]), "+f"(c[3])
        : "r"(a[0]), "r"(a[1]), "r"(a[2]), "r"(a[3]), "r"(b0), "r"(b1));
}

// ======================= scratch device globals ==============================
__device__ __align__(16) __nv_bfloat16 g_pbf[M_COLS * D_DIM];
__device__ float  g_sum_x[D_DIM];
__device__ float  g_sum_nx2;
__device__ int    g_nx2min_bits;
__device__ float  g_nx2[N_ROWS];
__device__ float4 g_pstat[M_COLS];   // {np2, invc, psi, 0}
__device__ float  g_ustar[M_COLS];   // per-column dot gate
__device__ double g_acc;
__device__ int    g_done;

// ======================= prep kernels ========================================
__global__ void init_kernel() {
    int t = threadIdx.x;
    if (t < D_DIM) g_sum_x[t] = 0.f;
    if (t == 0) { g_sum_nx2 = 0.f; g_acc = 0.0; g_nx2min_bits = 0x7f7fffff; g_done = 0; }
}

// per-row ||x||^2, column sums, global min ||x||^2
__global__ void xstats_kernel(const float* __restrict__ x) {
    __shared__ float ssx[8][128];
    __shared__ float ssn[8];
    __shared__ float ssm[8];
    int lane = threadIdx.x & 31;
    int wid  = threadIdx.x >> 5;
    int base = (blockIdx.x * 8 + wid) * 8;

    float sx0 = 0.f, sx1 = 0.f, sx2 = 0.f, sx3 = 0.f;
    float snx2 = 0.f, rmin = 3.4e38f;
    #pragma unroll
    for (int rr = 0; rr < 8; ++rr) {
        int row = base + rr;
        float4 v = ((const float4*)(x + (size_t)row * D_DIM))[lane];
        float d = v.x*v.x + v.y*v.y + v.z*v.z + v.w*v.w;
        snx2 += d;
        float dr = d;
        #pragma unroll
        for (int o = 16; o; o >>= 1) dr += __shfl_xor_sync(0xffffffffu, dr, o);
        if (lane == 0) { g_nx2[row] = dr; rmin = fminf(rmin, dr); }
        sx0 += v.x; sx1 += v.y; sx2 += v.z; sx3 += v.w;
    }
    ssx[wid][lane*4+0] = sx0; ssx[wid][lane*4+1] = sx1;
    ssx[wid][lane*4+2] = sx2; ssx[wid][lane*4+3] = sx3;
    #pragma unroll
    for (int o = 16; o; o >>= 1) snx2 += __shfl_xor_sync(0xffffffffu, snx2, o);
    if (lane == 0) { ssn[wid] = snx2; ssm[wid] = rmin; }
    __syncthreads();
    if (threadIdx.x < 128) {
        float s = 0.f;
        #pragma unroll
        for (int w = 0; w < 8; ++w) s += ssx[w][threadIdx.x];
        atomicAdd(&g_sum_x[threadIdx.x], s);
    }
    if (threadIdx.x == 0) {
        float s = 0.f, m = 3.4e38f;
        #pragma unroll
        for (int w = 0; w < 8; ++w) { s += ssn[w]; m = fminf(m, ssm[w]); }
        atomicAdd(&g_sum_nx2, s);
        atomicMin(&g_nx2min_bits, __float_as_int(m));   // all positive: int-order OK
    }
}

// warp-per-column: constants + conservative dot gate u*
__global__ void pstats_kernel(const float* __restrict__ p) {
    int j    = blockIdx.x * 8 + (threadIdx.x >> 5);
    int lane = threadIdx.x & 31;
    if (j >= M_COLS) return;
    float4 v = ((const float4*)(p + (size_t)j * D_DIM))[lane];
    float4 s = ((const float4*)g_sum_x)[lane];
    float np2   = v.x*v.x + v.y*v.y + v.z*v.z + v.w*v.w;
    float sxdot = v.x*s.x + v.y*s.y + v.z*s.z + v.w*s.w;
    __nv_bfloat162 h0 = __floats2bfloat162_rn(v.x, v.y);
    __nv_bfloat162 h1 = __floats2bfloat162_rn(v.z, v.w);
    uint2 hi = make_uint2(*(uint32_t*)&h0, *(uint32_t*)&h1);
    *(uint2*)(g_pbf + (size_t)j * D_DIM + lane * 4) = hi;
    #pragma unroll
    for (int o = 16; o; o >>= 1) {
        np2   += __shfl_xor_sync(0xffffffffu, np2, o);
        sxdot += __shfl_xor_sync(0xffffffffu, sxdot, o);
    }
    if (lane == 0) {
        float m      = __int_as_float(g_nx2min_bits);       // global min ||x||^2
        float ssd    = g_sum_nx2 + (float)N_ROWS * np2 - 2.f * sxdot;
        float invc   = rsqrtf(np2 * ssd);
        float inv_np = rsqrtf(np2);
        float psi    = asinf(K_CONST * (1.f - np2) * inv_np);
        float c1     = cosf(GAMMA_CONST + psi);             // > 0
        // hinge!=0 requires ratio>c1; conservative over rows (nx2>=m):
        //   stable root: s = q/(A*(sqrt(cC^2+q)+cC)), q = A(1-np2)(1-np2*m), u* = (E-s^2)/2
        float cC = c1 * sqrtf(np2 * ssd);
        float A  = 1.f + np2;
        float E  = fmaf(np2, m, 1.f);
        float q  = A * (1.f - np2) * (1.f - np2 * m);
        float sr = q / (A * (sqrtf(fmaf(cC, cC, q)) + cC));
        float us = 0.5f * (E - sr * sr) - 1e-4f;            // safety margin
        g_pstat[j] = make_float4(np2, invc, psi, 0.f);
        g_ustar[j] = us;
    }
}

// ======================= main fused kernel ===================================
// 256 CTAs x 64-row tiles, 256 threads (8 warps: 2 row x 4 col of 32x32),
// 2 CTAs/SM. 3-stage B ring => ONE barrier per tile; loads overlap MMA.
// SMEM map (bytes):
#define SM_RED 0                       // 8 floats + pad to 128
#define SM_A   128                     // 64x128 bf16 = 16384
#define SM_B   (SM_A + 16384)          // 3 x 32768
#define SMEM_TOTAL (SM_B + 3 * 32768)  // 114816  (x2 CTAs = 229632 <= 228KB carveout)
#define NTHREADS 256

// Tile stored as [rows][16 chunks of 16B]; phys chunk = c ^ (row & 7).
__device__ __forceinline__ uint32_t sw_off(int row, int c) {
    return (uint32_t)(row * 256 + ((c ^ (row & 7)) << 4));
}

__device__ __forceinline__ void load_b_tile(uint32_t sb, int buf, int t) {
    const int tid = threadIdx.x;
    const uint32_t bh = sb + SM_B + buf * 32768u;
    const size_t rbase = (size_t)t * 128 * D_DIM;
    #pragma unroll
    for (int i = 0; i < 8; ++i) {
        int idx = tid + i * NTHREADS;
        int row = idx >> 4, c = idx & 15;
        uint32_t off = sw_off(row, c);
        size_t src = rbase + (size_t)row * D_DIM + c * 8;
        CPA16(bh + off, (const void*)(g_pbf + src));
    }
}

// fast acos via A&S 4.4.45 (|err| <= 2e-8), sqrt.approx
__device__ __forceinline__ float acos_fast(float x) {
    float ax = fabsf(x);
    float s;
    asm("sqrt.approx.f32 %0, %1;" : "=f"(s) : "f"(1.0f - ax));
    float p = -0.0012624911f;
    p = fmaf(p, ax,  0.0066700901f);
    p = fmaf(p, ax, -0.0170881256f);
    p = fmaf(p, ax,  0.0308918810f);
    p = fmaf(p, ax, -0.0501743046f);
    p = fmaf(p, ax,  0.0889789874f);
    p = fmaf(p, ax, -0.2145988016f);
    p = fmaf(p, ax,  1.5707963050f);
    float r = s * p;
    return (x < 0.f) ? (3.14159265358979f - r) : r;
}

__global__ void __launch_bounds__(NTHREADS, 2)
main_kernel(const float* __restrict__ x, const int* __restrict__ labels,
            float* __restrict__ out) {
    extern __shared__ char smem[];
    const uint32_t sb = smem_u32(smem);
    const int tid = threadIdx.x;
    const int wid = tid >> 5, lane = tid & 31;
    const int rowBase = blockIdx.x * 64;
    const int warpRow = (wid & 1) * 32;      // 2 row-groups
    const int warpCol = (wid >> 1) * 32;     // 4 col-groups
    const int gid = lane >> 2, tig = lane & 3;
    const int lrow = lane & 15, side = lane >> 4, l7 = lane & 7;

    // ---- prologue: B tiles 0 and 1 into ring slots 0,1 ----
    load_b_tile(sb, 0, 0);
    CPA_COMMIT();
    load_b_tile(sb, 1, 1);
    CPA_COMMIT();

    // ---- A: load fp32 x tile (64 rows), round to bf16 in smem ----
    #pragma unroll
    for (int i = 0; i < 4; ++i) {
        int idx = tid + i * NTHREADS;          // 1024 16B-chunks
        int row = idx >> 4, c = idx & 15;
        const float4* src = (const float4*)(x + (size_t)(rowBase + row) * D_DIM + c * 8);
        float4 a = src[0], b = src[1];
        __nv_bfloat162 h0 = __floats2bfloat162_rn(a.x, a.y);
        __nv_bfloat162 h1 = __floats2bfloat162_rn(a.z, a.w);
        __nv_bfloat162 h2 = __floats2bfloat162_rn(b.x, b.y);
        __nv_bfloat162 h3 = __floats2bfloat162_rn(b.z, b.w);
        uint4 h = make_uint4(*(uint32_t*)&h0, *(uint32_t*)&h1,
                             *(uint32_t*)&h2, *(uint32_t*)&h3);
        *(uint4*)(smem + SM_A + sw_off(row, c)) = h;
    }

    // ---- per-thread row constants ----
    float bx4[4]; int lab4[4];
    #pragma unroll
    for (int mt = 0; mt < 2; ++mt)
        #pragma unroll
        for (int h = 0; h < 2; ++h) {
            int r = rowBase + warpRow + mt * 16 + gid + h * 8;
            bx4[mt * 2 + h]  = g_nx2[r];
            lab4[mt * 2 + h] = labels[r];
        }

    const uint32_t AH = sb + SM_A;
    float acc[2][4][4];   // [mt][nt][q], q = h*2+e
    float local = 0.f;
    int buf_cur = 0, buf_next = 2;   // tile t -> slot t%3; loads target (t+2)%3

    for (int t = 0; t < 16; ++t) {
        CPA_WAIT1();          // my groups for tile t done (tile t+1 may fly)
        __syncthreads();      // everyone's tile-t data visible; all readers of
                              // slot (t-1)%3 (== (t+2)%3) are past it
        if (t < 14) load_b_tile(sb, buf_next, t + 2);
        CPA_COMMIT();         // uniform group count (empty ok for t>=14)

        // ---- MMA: B from slot buf_cur, A from smem ----
        {
            const uint32_t BH = sb + SM_B + buf_cur * 32768u;
            #pragma unroll
            for (int mt = 0; mt < 2; ++mt)
                #pragma unroll
                for (int nt = 0; nt < 4; ++nt)
                    #pragma unroll
                    for (int q = 0; q < 4; ++q) acc[mt][nt][q] = 0.f;
            #pragma unroll
            for (int ks = 0; ks < 8; ++ks) {
                const uint32_t kc = (uint32_t)(((ks * 2 + side) ^ l7) << 4);
                uint32_t a0[4], a1[4];
                ldsm4(a0, AH + (uint32_t)(warpRow      + lrow) * 256 + kc);
                ldsm4(a1, AH + (uint32_t)(warpRow + 16 + lrow) * 256 + kc);
                #pragma unroll
                for (int tp = 0; tp < 2; ++tp) {
                    uint32_t b[4];
                    ldsm4(b, BH + (uint32_t)(warpCol + tp * 16 + lrow) * 256 + kc);
                    mma16816(acc[0][tp*2],   a0, b[0], b[2]);
                    mma16816(acc[0][tp*2+1], a0, b[1], b[3]);
                    mma16816(acc[1][tp*2],   a1, b[0], b[2]);
                    mma16816(acc[1][tp*2+1], a1, b[1], b[3]);
                }
            }
        }

        // ---- epilogue: per-column dot gate (ustar via L1-cached LDG) ----
        {
            const int colBase = t * 128 + warpCol;
            #pragma unroll
            for (int nt = 0; nt < 4; ++nt) {
                const int ci = colBase + nt * 8 + tig * 2;
                float2 us = __ldg((const float2*)(g_ustar + ci));
                float usmin = fminf(us.x, us.y);
                float d00 = acc[0][nt][0], d01 = acc[0][nt][1];
                float d10 = acc[0][nt][2], d11 = acc[0][nt][3];
                float d20 = acc[1][nt][0], d21 = acc[1][nt][1];
                float d30 = acc[1][nt][2], d31 = acc[1][nt][3];
                float dmax = fmaxf(fmaxf(fmaxf(d00, d01), fmaxf(d10, d11)),
                                   fmaxf(fmaxf(d20, d21), fmaxf(d30, d31)));
                if (dmax > usmin) {                                // cold, ~never
                    #pragma unroll
                    for (int e = 0; e < 2; ++e) {
                        float usv = e ? us.y : us.x;
                        float dv[4] = { e ? d01 : d00, e ? d11 : d10,
                                        e ? d21 : d20, e ? d31 : d30 };
                        const int c = ci + e;
                        #pragma unroll
                        for (int ri = 0; ri < 4; ++ri) {
                            float dot = dv[ri];
                            if (dot > usv && c != lab4[ri]) {
                                float4 ps  = g_pstat[c];
                                float bxv  = bx4[ri];
                                float num  = fmaf(ps.x, dot - (1.f + bxv), dot);
                                float tt   = fmaf(-2.f, dot, fmaf(ps.x, bxv, 1.f));
                                float ratio= num * ps.y * rsqrtf(tt);
                                float rc   = fminf(1.f, fmaxf(-1.f, ratio));
                                float ang  = fmaxf(0.f, acos_fast(rc) - ps.z);
                                local += fmaxf(0.f, GAMMA_CONST - ang);
                            }
                        }
                    }
                }
            }
            // ---- label elements (positive term), rare ownership check ----
            #pragma unroll
            for (int ri = 0; ri < 4; ++ri) {
                unsigned d = (unsigned)(lab4[ri] - colBase);
                if (d < 32u && (d & 6u) == 2u * (unsigned)tig) {
                    #pragma unroll
                    for (int nt = 0; nt < 4; ++nt)
                        if ((d >> 3) == (unsigned)nt) {
                            const int mt = ri >> 1, hh = ri & 1;
                            float dot = acc[mt][nt][hh * 2 + (d & 1u)];
                            float4 ps  = g_pstat[lab4[ri]];
                            float bxv  = bx4[ri];
                            float num  = fmaf(ps.x, dot - (1.f + bxv), dot);
                            float tt   = fmaf(-2.f, dot, fmaf(ps.x, bxv, 1.f));
                            float ratio= num * ps.y * rsqrtf(tt);
                            float rc   = fminf(1.f, fmaxf(-1.f, ratio));
                            local += fmaxf(0.f, acos_fast(rc) - ps.z);
                        }
                }
            }
        }

        buf_cur  = (buf_cur  == 2) ? 0 : buf_cur  + 1;
        buf_next = (buf_next == 2) ? 0 : buf_next + 1;
    }

    // ---- block reduction -> one double atomic; last CTA writes output ----
    #pragma unroll
    for (int o = 16; o; o >>= 1) local += __shfl_xor_sync(0xffffffffu, local, o);
    float* red = (float*)(smem + SM_RED);
    if (lane == 0) red[wid] = local;
    __syncthreads();
    if (tid == 0) {
        float s = 0.f;
        #pragma unroll
        for (int w = 0; w < 8; ++w) s += red[w];
        atomicAdd(&g_acc, (double)s);
        __threadfence();
        int ticket = atomicAdd(&g_done, 1);
        if (ticket == (int)gridDim.x - 1) {
            out[0] = (float)(g_acc / (double)N_ROWS);
            g_done = 0;                     // reset for next graph replay
        }
    }
}

// ======================= launch ==============================================
extern "C" void kernel_launch(void* const* d_in, const int* in_sizes, int n_in,
                              void* d_out, int out_size) {
    const float* x      = (const float*)d_in[0];
    const float* p      = (const float*)d_in[1];
    const int*   labels = (const int*)d_in[2];
    float* out = (float*)d_out;

    cudaFuncSetAttribute(main_kernel, cudaFuncAttributeMaxDynamicSharedMemorySize, SMEM_TOTAL);

    init_kernel<<<1, 128>>>();
    xstats_kernel<<<256, 256>>>(x);
    pstats_kernel<<<256, 256>>>(p);
    main_kernel<<<256, NTHREADS, SMEM_TOTAL>>>(x, labels, out);
}

// round 17
// speedup vs baseline: 1.1422x; 1.0714x over previous
#include <cuda_runtime.h>
#include <cuda_bf16.h>
#include <cstdint>

#define N_ROWS 16384
#define M_COLS 2048
#define D_DIM  128
#define K_CONST 0.1f
#define GAMMA_CONST 1.0f

// ======================= PTX helpers ========================================
__device__ __forceinline__ uint32_t smem_u32(const void* p) {
    uint32_t a;
    asm("{ .reg .u64 t; cvta.to.shared.u64 t, %1; cvt.u32.u64 %0, t; }" : "=r"(a) : "l"(p));
    return a;
}
#define CPA16(dst, src) \
    asm volatile("cp.async.cg.shared.global [%0], [%1], 16;" :: "r"(dst), "l"(src))
#define CPA_COMMIT() asm volatile("cp.async.commit_group;" ::: "memory")
#define CPA_WAIT0()  asm volatile("cp.async.wait_group 0;" ::: "memory")

__device__ __forceinline__ void ldsm4(uint32_t* r, uint32_t addr) {
    asm volatile("ldmatrix.sync.aligned.m8n8.x4.shared.b16 {%0,%1,%2,%3}, [%4];"
        : "=r"(r[0]), "=r"(r[1]), "=r"(r[2]), "=r"(r[3]) : "r"(addr));
}
__device__ __forceinline__ void mma16816(float* c, const uint32_t* a, uint32_t b0, uint32_t b1) {
    asm volatile("mma.sync.aligned.m16n8k16.row.col.f32.bf16.bf16.f32 "
        "{%0,%1,%2,%3}, {%4,%5,%6,%7}, {%8,%9}, {%0,%1,%2,%3};"
        : "+f"(c[0]), "+f"(c[1]), "+f"(c[2]), "+f"(c[3])
        : "r"(a[0]), "r"(a[1]), "r"(a[2]), "r"(a[3]), "r"(b0), "r"(b1));
}

// ======================= scratch device globals (all zero-init) ==============
__device__ __align__(16) __nv_bfloat16 g_pbf[M_COLS * D_DIM];
__device__ float  g_sum_x[D_DIM];          // zero-init; reset by main's last CTA
__device__ float  g_sum_nx2;               // idem
__device__ float  g_nx2[N_ROWS];
__device__ float4 g_pstat[M_COLS];         // {np2, invc, psi, 0}
__device__ float  g_ustar[M_COLS];         // per-column dot gate
__device__ double g_acc;                   // zero-init; reset by last CTA
__device__ int    g_done;                  // idem

// ======================= prep kernels ========================================
// per-row ||x||^2 + column sums (block-level smem reduce, few atomics)
__global__ void xstats_kernel(const float* __restrict__ x) {
    __shared__ float ssx[8][128];
    __shared__ float ssn[8];
    int lane = threadIdx.x & 31;
    int wid  = threadIdx.x >> 5;
    int base = (blockIdx.x * 8 + wid) * 8;

    float sx0 = 0.f, sx1 = 0.f, sx2 = 0.f, sx3 = 0.f;
    float snx2 = 0.f;
    #pragma unroll
    for (int rr = 0; rr < 8; ++rr) {
        int row = base + rr;
        float4 v = ((const float4*)(x + (size_t)row * D_DIM))[lane];
        float d = v.x*v.x + v.y*v.y + v.z*v.z + v.w*v.w;
        snx2 += d;
        float dr = d;
        #pragma unroll
        for (int o = 16; o; o >>= 1) dr += __shfl_xor_sync(0xffffffffu, dr, o);
        if (lane == 0) g_nx2[row] = dr;
        sx0 += v.x; sx1 += v.y; sx2 += v.z; sx3 += v.w;
    }
    ssx[wid][lane*4+0] = sx0; ssx[wid][lane*4+1] = sx1;
    ssx[wid][lane*4+2] = sx2; ssx[wid][lane*4+3] = sx3;
    #pragma unroll
    for (int o = 16; o; o >>= 1) snx2 += __shfl_xor_sync(0xffffffffu, snx2, o);
    if (lane == 0) ssn[wid] = snx2;
    __syncthreads();
    if (threadIdx.x < 128) {
        float s = 0.f;
        #pragma unroll
        for (int w = 0; w < 8; ++w) s += ssx[w][threadIdx.x];
        atomicAdd(&g_sum_x[threadIdx.x], s);
    }
    if (threadIdx.x == 0) {
        float s = 0.f;
        #pragma unroll
        for (int w = 0; w < 8; ++w) s += ssn[w];
        atomicAdd(&g_sum_nx2, s);
    }
}

// warp-per-column: constants + conservative dot gate u* (m = 0, valid for all nx2>=0)
__global__ void pstats_kernel(const float* __restrict__ p) {
    int j    = blockIdx.x * 8 + (threadIdx.x >> 5);
    int lane = threadIdx.x & 31;
    if (j >= M_COLS) return;
    float4 v = ((const float4*)(p + (size_t)j * D_DIM))[lane];
    float4 s = ((const float4*)g_sum_x)[lane];
    float np2   = v.x*v.x + v.y*v.y + v.z*v.z + v.w*v.w;
    float sxdot = v.x*s.x + v.y*s.y + v.z*s.z + v.w*s.w;
    __nv_bfloat162 h0 = __floats2bfloat162_rn(v.x, v.y);
    __nv_bfloat162 h1 = __floats2bfloat162_rn(v.z, v.w);
    uint2 hi = make_uint2(*(uint32_t*)&h0, *(uint32_t*)&h1);
    *(uint2*)(g_pbf + (size_t)j * D_DIM + lane * 4) = hi;
    #pragma unroll
    for (int o = 16; o; o >>= 1) {
        np2   += __shfl_xor_sync(0xffffffffu, np2, o);
        sxdot += __shfl_xor_sync(0xffffffffu, sxdot, o);
    }
    if (lane == 0) {
        float ssd    = g_sum_nx2 + (float)N_ROWS * np2 - 2.f * sxdot;
        float invc   = rsqrtf(np2 * ssd);
        float inv_np = rsqrtf(np2);
        float psi    = asinf(K_CONST * (1.f - np2) * inv_np);
        float c1     = cosf(GAMMA_CONST + psi);             // > 0
        // hinge!=0 requires ratio>c1; conservative over rows with nx2>=0 (m=0):
        //   stable root: sr = q/(A*(sqrt(cC^2+q)+cC)), q = A(1-np2), u* = (1-sr^2)/2
        float cC = c1 * sqrtf(np2 * ssd);
        float A  = 1.f + np2;
        float q  = A * (1.f - np2);
        float sr = q / (A * (sqrtf(fmaf(cC, cC, q)) + cC));
        float us = 0.5f * (1.f - sr * sr) - 1e-4f;          // safety margin
        g_pstat[j] = make_float4(np2, invc, psi, 0.f);
        g_ustar[j] = us;
    }
}

// ======================= main fused kernel (R13 champion config) =============
// 256 CTAs x 64-row tiles, 256 threads (8 warps: 2 row x 4 col of 32x32), 2 CTAs/SM.
// SMEM map (bytes):
#define SM_RED 0                       // 8 floats + pad
#define SM_US  128                     // ustar: 2048 * 4 = 8192
#define SM_A   (SM_US + 8192)          // 64x128 bf16 = 16384
#define SM_B   (SM_A + 16384)          // 2 x 32768
#define SMEM_TOTAL (SM_B + 2 * 32768)  // 90240  (x2 CTAs = 180KB, fits)
#define NTHREADS 256

// Tile stored as [rows][16 chunks of 16B]; phys chunk = c ^ (row & 7).
__device__ __forceinline__ uint32_t sw_off(int row, int c) {
    return (uint32_t)(row * 256 + ((c ^ (row & 7)) << 4));
}

__device__ __forceinline__ void load_b_tile(uint32_t sb, int buf, int t) {
    const int tid = threadIdx.x;
    const uint32_t bh = sb + SM_B + buf * 32768u;
    const size_t rbase = (size_t)t * 128 * D_DIM;
    #pragma unroll
    for (int i = 0; i < 8; ++i) {
        int idx = tid + i * NTHREADS;
        int row = idx >> 4, c = idx & 15;
        uint32_t off = sw_off(row, c);
        size_t src = rbase + (size_t)row * D_DIM + c * 8;
        CPA16(bh + off, (const void*)(g_pbf + src));
    }
}

// fast acos via A&S 4.4.45 (|err| <= 2e-8), sqrt.approx
__device__ __forceinline__ float acos_fast(float x) {
    float ax = fabsf(x);
    float s;
    asm("sqrt.approx.f32 %0, %1;" : "=f"(s) : "f"(1.0f - ax));
    float p = -0.0012624911f;
    p = fmaf(p, ax,  0.0066700901f);
    p = fmaf(p, ax, -0.0170881256f);
    p = fmaf(p, ax,  0.0308918810f);
    p = fmaf(p, ax, -0.0501743046f);
    p = fmaf(p, ax,  0.0889789874f);
    p = fmaf(p, ax, -0.2145988016f);
    p = fmaf(p, ax,  1.5707963050f);
    float r = s * p;
    return (x < 0.f) ? (3.14159265358979f - r) : r;
}

__global__ void __launch_bounds__(NTHREADS, 2)
main_kernel(const float* __restrict__ x, const int* __restrict__ labels,
            float* __restrict__ out) {
    extern __shared__ char smem[];
    const uint32_t sb = smem_u32(smem);
    const int tid = threadIdx.x;
    const int wid = tid >> 5, lane = tid & 31;
    const int rowBase = blockIdx.x * 64;
    const int warpRow = (wid & 1) * 32;      // 2 row-groups
    const int warpCol = (wid >> 1) * 32;     // 4 col-groups
    const int gid = lane >> 2, tig = lane & 3;
    const int lrow = lane & 15, side = lane >> 4, l7 = lane & 7;

    // ---- async loads: ustar (8KB), B tiles 0 and 1 ----
    if (tid < 128) {
        CPA16(sb + SM_US + tid * 16, (const void*)(g_ustar + tid * 4));
        CPA16(sb + SM_US + 2048 + tid * 16, (const void*)(g_ustar + 512 + tid * 4));
        CPA16(sb + SM_US + 4096 + tid * 16, (const void*)(g_ustar + 1024 + tid * 4));
        CPA16(sb + SM_US + 6144 + tid * 16, (const void*)(g_ustar + 1536 + tid * 4));
    }
    load_b_tile(sb, 0, 0);
    load_b_tile(sb, 1, 1);
    CPA_COMMIT();

    // ---- A: load fp32 x tile (64 rows), round to bf16 in smem ----
    #pragma unroll
    for (int i = 0; i < 4; ++i) {
        int idx = tid + i * NTHREADS;          // 1024 16B-chunks
        int row = idx >> 4, c = idx & 15;
        const float4* src = (const float4*)(x + (size_t)(rowBase + row) * D_DIM + c * 8);
        float4 a = src[0], b = src[1];
        __nv_bfloat162 h0 = __floats2bfloat162_rn(a.x, a.y);
        __nv_bfloat162 h1 = __floats2bfloat162_rn(a.z, a.w);
        __nv_bfloat162 h2 = __floats2bfloat162_rn(b.x, b.y);
        __nv_bfloat162 h3 = __floats2bfloat162_rn(b.z, b.w);
        uint4 h = make_uint4(*(uint32_t*)&h0, *(uint32_t*)&h1,
                             *(uint32_t*)&h2, *(uint32_t*)&h3);
        *(uint4*)(smem + SM_A + sw_off(row, c)) = h;
    }

    // ---- per-thread row constants ----
    float bx4[4]; int lab4[4];
    #pragma unroll
    for (int mt = 0; mt < 2; ++mt)
        #pragma unroll
        for (int h = 0; h < 2; ++h) {
            int r = rowBase + warpRow + mt * 16 + gid + h * 8;
            bx4[mt * 2 + h]  = g_nx2[r];
            lab4[mt * 2 + h] = labels[r];
        }

    CPA_WAIT0();
    __syncthreads();

    const uint32_t AH = sb + SM_A;
    const float* usp = (const float*)(smem + SM_US);

    float acc[2][2][4][4];   // [bank][mt][nt][q]
    float local = 0.f;

    // ---- MMA for one tile from buffer `buf` into bank `pb` ----
    auto mma_tile = [&](int buf, int pb) {
        const uint32_t BH = sb + SM_B + buf * 32768u;
        #pragma unroll
        for (int mt = 0; mt < 2; ++mt)
            #pragma unroll
            for (int nt = 0; nt < 4; ++nt)
                #pragma unroll
                for (int q = 0; q < 4; ++q) acc[pb][mt][nt][q] = 0.f;
        #pragma unroll
        for (int ks = 0; ks < 8; ++ks) {
            const uint32_t kc = (uint32_t)(((ks * 2 + side) ^ l7) << 4);
            uint32_t a0[4], a1[4];
            ldsm4(a0, AH + (uint32_t)(warpRow      + lrow) * 256 + kc);
            ldsm4(a1, AH + (uint32_t)(warpRow + 16 + lrow) * 256 + kc);
            #pragma unroll
            for (int tp = 0; tp < 2; ++tp) {
                uint32_t b[4];
                ldsm4(b, BH + (uint32_t)(warpCol + tp * 16 + lrow) * 256 + kc);
                mma16816(acc[pb][0][tp*2],   a0, b[0], b[2]);
                mma16816(acc[pb][0][tp*2+1], a0, b[1], b[3]);
                mma16816(acc[pb][1][tp*2],   a1, b[0], b[2]);
                mma16816(acc[pb][1][tp*2+1], a1, b[1], b[3]);
            }
        }
    };

    // ---- epilogue for tile t from bank pb ----
    auto epilogue = [&](int t, int pb) {
        const int colBase = t * 128 + warpCol;
        #pragma unroll
        for (int nt = 0; nt < 4; ++nt) {
            const int ci = colBase + nt * 8 + tig * 2;
            float2 us = *(const float2*)(usp + ci);
            float usmin = fminf(us.x, us.y);
            float d00 = acc[pb][0][nt][0], d01 = acc[pb][0][nt][1];
            float d10 = acc[pb][0][nt][2], d11 = acc[pb][0][nt][3];
            float d20 = acc[pb][1][nt][0], d21 = acc[pb][1][nt][1];
            float d30 = acc[pb][1][nt][2], d31 = acc[pb][1][nt][3];
            float dmax = fmaxf(fmaxf(fmaxf(d00, d01), fmaxf(d10, d11)),
                               fmaxf(fmaxf(d20, d21), fmaxf(d30, d31)));
            if (dmax > usmin) {                                // cold, ~never
                #pragma unroll
                for (int e = 0; e < 2; ++e) {
                    float usv = e ? us.y : us.x;
                    float dv[4] = { e ? d01 : d00, e ? d11 : d10,
                                    e ? d21 : d20, e ? d31 : d30 };
                    const int c = ci + e;
                    #pragma unroll
                    for (int ri = 0; ri < 4; ++ri) {
                        float dot = dv[ri];
                        if (dot > usv && c != lab4[ri]) {
                            float4 ps  = g_pstat[c];
                            float bxv  = bx4[ri];
                            float num  = fmaf(ps.x, dot - (1.f + bxv), dot);
                            float tt   = fmaf(-2.f, dot, fmaf(ps.x, bxv, 1.f));
                            float ratio= num * ps.y * rsqrtf(tt);
                            float rc   = fminf(1.f, fmaxf(-1.f, ratio));
                            float ang  = fmaxf(0.f, acos_fast(rc) - ps.z);
                            local += fmaxf(0.f, GAMMA_CONST - ang);
                        }
                    }
                }
            }
        }
        // ---- label elements (positive term), rare ownership check ----
        #pragma unroll
        for (int ri = 0; ri < 4; ++ri) {
            unsigned d = (unsigned)(lab4[ri] - colBase);
            if (d < 32u && (d & 6u) == 2u * (unsigned)tig) {
                #pragma unroll
                for (int nt = 0; nt < 4; ++nt)
                    if ((d >> 3) == (unsigned)nt) {
                        const int mt = ri >> 1, hh = ri & 1;
                        float dot = (d & 1u) ? acc[pb][mt][nt][hh*2+1]
                                             : acc[pb][mt][nt][hh*2];
                        float4 ps  = g_pstat[lab4[ri]];
                        float bxv  = bx4[ri];
                        float num  = fmaf(ps.x, dot - (1.f + bxv), dot);
                        float tt   = fmaf(-2.f, dot, fmaf(ps.x, bxv, 1.f));
                        float ratio= num * ps.y * rsqrtf(tt);
                        float rc   = fminf(1.f, fmaxf(-1.f, ratio));
                        local += fmaxf(0.f, acos_fast(rc) - ps.z);
                    }
            }
        }
    };

    // ---- pipelined loop: MMA(t+1) issued before epilogue(t) ----
    mma_tile(0, 0);
    for (int tb = 0; tb < 16; tb += 2) {
        #pragma unroll
        for (int u = 0; u < 2; ++u) {
            const int t = tb + u;
            if (t < 15) {
                CPA_WAIT0();
                __syncthreads();
                if (t < 14) { load_b_tile(sb, t & 1, t + 2); CPA_COMMIT(); }
                mma_tile((t + 1) & 1, (u + 1) & 1);
            }
            epilogue(t, u);
        }
    }

    // ---- block reduction -> one double atomic; last CTA finishes + resets ----
    #pragma unroll
    for (int o = 16; o; o >>= 1) local += __shfl_xor_sync(0xffffffffu, local, o);
    float* red = (float*)(smem + SM_RED);
    if (lane == 0) red[wid] = local;
    __syncthreads();
    if (tid == 0) {
        float s = 0.f;
        #pragma unroll
        for (int w = 0; w < 8; ++w) s += red[w];
        atomicAdd(&g_acc, (double)s);
        __threadfence();
        int ticket = atomicAdd(&g_done, 1);
        if (ticket == (int)gridDim.x - 1) {
            out[0] = (float)(g_acc / (double)N_ROWS);
            // self-clean for next replay (deterministic state)
            g_acc = 0.0;
            g_sum_nx2 = 0.f;
            #pragma unroll
            for (int i = 0; i < D_DIM; ++i) g_sum_x[i] = 0.f;
            g_done = 0;
        }
    }
}

// ======================= launch ==============================================
extern "C" void kernel_launch(void* const* d_in, const int* in_sizes, int n_in,
                              void* d_out, int out_size) {
    const float* x      = (const float*)d_in[0];
    const float* p      = (const float*)d_in[1];
    const int*   labels = (const int*)d_in[2];
    float* out = (float*)d_out;

    cudaFuncSetAttribute(main_kernel, cudaFuncAttributeMaxDynamicSharedMemorySize, SMEM_TOTAL);

    xstats_kernel<<<256, 256>>>(x);
    pstats_kernel<<<256, 256>>>(p);
    main_kernel<<<256, NTHREADS, SMEM_TOTAL>>>(x, labels, out);
}